// round 9
// baseline (speedup 1.0000x reference)
#include <cuda_runtime.h>
#include <math.h>

// Problem constants (N=128 images, P=16 control points, S=128 grid)
#define NIMG 128
#define NP   16
#define SDIM 128
#define RAD  4                 // 9-tap Gaussian: dropped taps <= 1.1e-7 (safe vs 1e-3 tol)
#define KW   (2*RAD+1)

// Histogram in gmem (L2-resident): [NIMG][HR][HP]
#define HR   129               // x in 0..128
#define HP   132               // y pitch (mult of 4)
#define HP4  (HP/4)            // 33 float4 per row

// Kernel H (histogram)
#define HT   512
#define H_SMEM_F (HR*HP)       // 17028 floats

// Kernel B (convolution): 4 slices of 32 rows per image
#define BT     256
#define SLICES 4
#define SR     32
#define LR     (SR + 2*RAD)    // 40 hist rows loaded per slice
#define M1P    137             // m1 pitch: cols 0..136 = y+4 (y in 0..128) + zero halo; 137%32=9 -> conflict-free
#define RESP   129             // result staging pitch (129%32=1 -> conflict-free)
#define B_SMEM_F (LR*HP + SR*M1P)   // 5280 + 4384 = 9664 floats (~38.7 KB)

__device__ __align__(16) float g_hist[NIMG * HR * HP];

// Compile-time taps exp(-d^2), d = idx-RAD  -> FFMA immediates
#define W0 1.1253517471925912e-7f
#define W1 1.2340980408667956e-4f
#define W2 0.018315638888734179f
#define W3 0.36787944117144233f
#define W4 1.0f
__device__ __constant__ const float Wc[KW] = { W0, W1, W2, W3, W4, W3, W2, W1, W0 };

// ---------------- Kernel H: per-image histogram of rounded interpolated points --------
__global__ __launch_bounds__(HT)
void hist_kernel(const float* __restrict__ points)
{
    extern __shared__ float h[];           // [HR][HP]
    const int n   = blockIdx.x;
    const int tid = threadIdx.x;

    // zero
    {
        float4 z = make_float4(0.f, 0.f, 0.f, 0.f);
        float4* h4 = (float4*)h;
        for (int i = tid; i < H_SMEM_F / 4; i += HT) h4[i] = z;
    }
    __syncthreads();

    // K = (P-1)*S = 1920 interpolated points
    const float inv = 1.0f / (float)SDIM;
    const float* pn = points + n * NP * 2;
    for (int k = tid; k < (NP - 1) * SDIM; k += HT) {
        int seg = k >> 7;
        int i   = k & 127;
        float t   = (float)i * inv;
        float omt = 1.0f - t;
        float x0 = pn[seg * 2 + 0];
        float y0 = pn[seg * 2 + 1];
        float x1 = pn[seg * 2 + 2];
        float y1 = pn[seg * 2 + 3];
        // match XLA: mul, mul, add — no fma contraction
        float x = __fadd_rn(__fmul_rn(omt, x0), __fmul_rn(t, x1));
        float y = __fadd_rn(__fmul_rn(omt, y0), __fmul_rn(t, y1));
        int ix = (int)rintf(x);            // round-half-to-even, 0..128
        int iy = (int)rintf(y);
        atomicAdd(&h[ix * HP + iy], 1.0f);
    }
    __syncthreads();

    // copy out (coalesced float4)
    {
        float4* src = (float4*)h;
        float4* dst = (float4*)(g_hist + (size_t)n * HR * HP);
        for (int i = tid; i < H_SMEM_F / 4; i += HT) dst[i] = src[i];
    }
}

// ---------------- Kernel B: one 32-row output slice per CTA ---------------------------
__global__ __launch_bounds__(BT)
void conv_kernel(float* __restrict__ out)
{
    extern __shared__ float sm[];
    float* hs = sm;                  // [LR][HP] hist slab; later reused as res[SR][RESP]
    float* m1 = sm + LR * HP;        // [SR][M1P]

    const int n   = blockIdx.x >> 2;
    const int q   = blockIdx.x & 3;
    const int s0  = q * SR;
    const int tid = threadIdx.x;

    // ---- load hist rows s0-4 .. s0+35 (OOB rows -> 0) ----
    {
        const float4* src = (const float4*)(g_hist + (size_t)n * HR * HP);
        float4* dst = (float4*)hs;
        float4 z = make_float4(0.f, 0.f, 0.f, 0.f);
        for (int i = tid; i < LR * HP4; i += BT) {
            int r  = i / HP4;
            int c4 = i - r * HP4;
            int gr = s0 - RAD + r;
            dst[i] = (gr >= 0 && gr < HR) ? __ldg(&src[gr * HP4 + c4]) : z;
        }
        // zero m1 halo cols 0..3 and 133..136 (interior overwritten below)
        for (int i = tid; i < SR * 2 * RAD; i += BT) {
            int r = i / (2 * RAD);
            int c = i - r * (2 * RAD);
            int col = (c < RAD) ? c : (M1P - 2 * RAD + c);
            m1[r * M1P + col] = 0.0f;
        }
    }
    __syncthreads();

    // ---- conv along x: m1[s][y+4] = sum_d W[d]*hs[s+d][y]; lanes -> consecutive y ----
    for (int item = tid; item < 4 * 129; item += BT) {
        int sg = item / 129;
        int y  = item - sg * 129;      // 0..128
        int sbase = sg * 8;
        float v[8 + KW - 1];           // 16
#pragma unroll
        for (int j = 0; j < 8 + KW - 1; ++j)
            v[j] = hs[(sbase + j) * HP + y];
#pragma unroll
        for (int i = 0; i < 8; ++i) {
            float acc = 0.0f;
#pragma unroll
            for (int d = 0; d < KW; ++d)
                acc = fmaf(Wc[d], v[i + d], acc);
            m1[(sbase + i) * M1P + (y + RAD)] = acc;
        }
    }
    __syncthreads();

    // ---- conv along y + tanh -> staged into res (reuses hs region) ----
    // lanes -> consecutive s; m1 lane stride M1P (bank stride 9) conflict-free
    float* res = hs;                   // [SR][RESP]
    for (int item = tid; item < SR * 16; item += BT) {
        int s  = item & 31;
        int tb = (item >> 5) * 8;
        float v[8 + KW - 1];
#pragma unroll
        for (int j = 0; j < 8 + KW - 1; ++j)
            v[j] = m1[s * M1P + tb + j];
#pragma unroll
        for (int i = 0; i < 8; ++i) {
            float acc = 0.0f;
#pragma unroll
            for (int d = 0; d < KW; ++d)
                acc = fmaf(Wc[d], v[i + d], acc);
            // tanh(x), x >= 0:  1 - 2/(e^{2x}+1); inf-safe
            float e = __expf(2.0f * acc);
            res[s * RESP + tb + i] = 1.0f - __fdividef(2.0f, e + 1.0f);
        }
    }
    __syncthreads();

    // ---- coalesced vectorized store: res -> out[n][s0..s0+31][*] ----
    {
        float4* dst = (float4*)(out + ((size_t)n * SDIM + s0) * SDIM);
        for (int i = tid; i < SR * (SDIM / 4); i += BT) {
            int s  = i >> 5;
            int c4 = (i & 31) * 4;
            const float* r = res + s * RESP + c4;
            dst[i] = make_float4(r[0], r[1], r[2], r[3]);
        }
    }
}

extern "C" void kernel_launch(void* const* d_in, const int* in_sizes, int n_in,
                              void* d_out, int out_size)
{
    const float* points = (const float*)d_in[0];
    float* out = (float*)d_out;

    cudaFuncSetAttribute(hist_kernel,
                         cudaFuncAttributeMaxDynamicSharedMemorySize,
                         (int)(H_SMEM_F * sizeof(float)));
    cudaFuncSetAttribute(conv_kernel,
                         cudaFuncAttributeMaxDynamicSharedMemorySize,
                         (int)(B_SMEM_F * sizeof(float)));

    hist_kernel<<<NIMG, HT, H_SMEM_F * sizeof(float)>>>(points);
    conv_kernel<<<NIMG * SLICES, BT, B_SMEM_F * sizeof(float)>>>(out);
}

// round 10
// speedup vs baseline: 1.3824x; 1.3824x over previous
#include <cuda_runtime.h>
#include <math.h>

// Problem constants (N=128 images, P=16 control points, S=128 grid)
#define NIMG 128
#define NP   16
#define SDIM 128
#define RAD  4                 // 9-tap Gaussian: dropped taps <= 1.1e-7 (safe vs 1e-3 tol)
#define KW   (2*RAD+1)

#define BT     256             // threads per CTA
#define SLICES 4               // CTAs per image
#define SR     32              // output rows per CTA
#define LR     (SR + 2*RAD)    // 40 histogram rows per slice (with halo)
#define HP     132             // hist y pitch (y in 0..128), mult of 4
#define M1P    137             // m1 pitch; 137%32=9 coprime -> conflict-free column walks
#define RESP   129             // result staging pitch; 129%32=1 conflict-free
#define B_SMEM_F (LR*HP + SR*M1P)   // 5280 + 4384 = 9664 floats (~38.7 KB)

// Compile-time taps exp(-d^2), d = idx-RAD  -> FFMA immediates
__device__ __constant__ const float Wc[KW] = {
    1.1253517471925912e-7f, 1.2340980408667956e-4f, 0.018315638888734179f,
    0.36787944117144233f, 1.0f, 0.36787944117144233f,
    0.018315638888734179f, 1.2340980408667956e-4f, 1.1253517471925912e-7f
};

__global__ __launch_bounds__(BT)
void plotline2_kernel(const float* __restrict__ points, float* __restrict__ out)
{
    extern __shared__ float sm[];
    float* hs = sm;                  // [LR][HP] slice histogram; later reused as res[SR][RESP]
    float* m1 = sm + LR * HP;        // [SR][M1P]

    const int n   = blockIdx.x >> 2;
    const int q   = blockIdx.x & 3;
    const int s0  = q * SR;
    const int tid = threadIdx.x;

    // ---- zero hist slab + m1 halo columns ----
    {
        float4 z = make_float4(0.f, 0.f, 0.f, 0.f);
        float4* h4 = (float4*)hs;
        for (int i = tid; i < (LR * HP) / 4; i += BT) h4[i] = z;
        for (int i = tid; i < SR * 2 * RAD; i += BT) {
            int r = i / (2 * RAD);
            int c = i - r * (2 * RAD);
            int col = (c < RAD) ? c : (M1P - 2 * RAD + c);   // 0..3 or 133..136
            m1[r * M1P + col] = 0.0f;
        }
    }
    __syncthreads();

    // ---- stage 1: interpolate all 1920 points, histogram the ones in our x-window ----
    const float inv = 1.0f / (float)SDIM;
    const float* pn = points + n * NP * 2;
    const int lrbase = s0 - RAD;
    for (int k = tid; k < (NP - 1) * SDIM; k += BT) {
        int seg = k >> 7;
        int i   = k & 127;
        float t   = (float)i * inv;
        float omt = 1.0f - t;
        float x0 = pn[seg * 2 + 0];
        float y0 = pn[seg * 2 + 1];
        float x1 = pn[seg * 2 + 2];
        float y1 = pn[seg * 2 + 3];
        // match XLA: mul, mul, add — no fma contraction
        float x = __fadd_rn(__fmul_rn(omt, x0), __fmul_rn(t, x1));
        float y = __fadd_rn(__fmul_rn(omt, y0), __fmul_rn(t, y1));
        int ix = (int)rintf(x);            // round-half-to-even, 0..128
        int iy = (int)rintf(y);
        int lr = ix - lrbase;              // local hist row
        if ((unsigned)lr < (unsigned)LR)
            atomicAdd(&hs[lr * HP + iy], 1.0f);
    }
    __syncthreads();

    // ---- stage 2: conv along x: m1[s][y+RAD] = sum_d W[d]*hs[s+d][y] ----
    // lanes -> consecutive y (stride 1, conflict-free)
    for (int item = tid; item < 4 * 129; item += BT) {
        int sg = item / 129;
        int y  = item - sg * 129;          // 0..128
        int sbase = sg * 8;
        float v[8 + KW - 1];               // 16
#pragma unroll
        for (int j = 0; j < 8 + KW - 1; ++j)
            v[j] = hs[(sbase + j) * HP + y];
#pragma unroll
        for (int i = 0; i < 8; ++i) {
            float acc = 0.0f;
#pragma unroll
            for (int d = 0; d < KW; ++d)
                acc = fmaf(Wc[d], v[i + d], acc);
            m1[(sbase + i) * M1P + (y + RAD)] = acc;
        }
    }
    __syncthreads();

    // ---- stage 3: conv along y + tanh -> staged into res (reuses hs region) ----
    // lanes -> consecutive s; m1 lane stride M1P (bank stride 9) conflict-free
    float* res = hs;                       // [SR][RESP]
    for (int item = tid; item < SR * 16; item += BT) {
        int s  = item & 31;
        int tb = (item >> 5) * 8;
        float v[8 + KW - 1];
#pragma unroll
        for (int j = 0; j < 8 + KW - 1; ++j)
            v[j] = m1[s * M1P + tb + j];
#pragma unroll
        for (int i = 0; i < 8; ++i) {
            float acc = 0.0f;
#pragma unroll
            for (int d = 0; d < KW; ++d)
                acc = fmaf(Wc[d], v[i + d], acc);
            // tanh(x), x >= 0:  1 - 2/(e^{2x}+1); inf-safe
            float e = __expf(2.0f * acc);
            res[s * RESP + tb + i] = 1.0f - __fdividef(2.0f, e + 1.0f);
        }
    }
    __syncthreads();

    // ---- stage 4: coalesced vectorized store -> out[n][s0..s0+31][*] ----
    {
        float4* dst = (float4*)(out + ((size_t)n * SDIM + s0) * SDIM);
        for (int i = tid; i < SR * (SDIM / 4); i += BT) {
            int s  = i >> 5;
            int c4 = (i & 31) * 4;
            const float* r = res + s * RESP + c4;
            dst[i] = make_float4(r[0], r[1], r[2], r[3]);
        }
    }
}

extern "C" void kernel_launch(void* const* d_in, const int* in_sizes, int n_in,
                              void* d_out, int out_size)
{
    const float* points = (const float*)d_in[0];
    float* out = (float*)d_out;

    size_t smem = B_SMEM_F * sizeof(float);   // ~38.7 KB
    cudaFuncSetAttribute(plotline2_kernel,
                         cudaFuncAttributeMaxDynamicSharedMemorySize, (int)smem);
    plotline2_kernel<<<NIMG * SLICES, BT, smem>>>(points, out);
}